// round 3
// baseline (speedup 1.0000x reference)
#include <cuda_runtime.h>
#include <cuda_bf16.h>

// ---------------------------------------------------------------------------
// GLACrossAttention: B=2 QL=1024 KL=4096 HID=2048 H=16 HD=128 RD=64
//                    G=4 HPG=4 QLR=512 LAT=256 KVP=1024 EPS=1e-6
// Round 0: full fp32 pipeline (correctness + baseline).
// ---------------------------------------------------------------------------

#define B_    2
#define QL_   1024
#define KL_   4096
#define HID_  2048
#define H_    16
#define HD_   128
#define RD_   64
#define G_    4
#define QLR_  512
#define LAT_  256
#define EPS_  1e-6f

// Scratch (device globals; allocation-free contract)
__device__ float g_qlat [B_*QL_*QLR_];            //  4 MB
__device__ float g_qfull[B_*QL_*H_*(HD_+RD_)];    // 24 MB
__device__ float g_ckv  [B_*KL_*G_*LAT_];         // 32 MB
__device__ float g_kv   [(size_t)B_*KL_*H_*2*HD_];// 128 MB
__device__ float g_attn [B_*QL_*H_*HD_];          // 16 MB

// ---------------------------------------------------------------------------
// Generic fp32 GEMM: C[M,N] = A[M,K] @ B[K,N], 128x128x16 tile, 8x8 microtile.
// All M,N,K used are multiples of 128/128/16 -> no bounds checks.
// Batched over gridDim.z via element strides (for the grouped einsum).
// ---------------------------------------------------------------------------
#define BM 128
#define BN 128
#define BK 16

__global__ __launch_bounds__(256) void gemm_f32(
    const float* __restrict__ A, int lda, long aBatch,
    const float* __restrict__ Bm, int ldb, long bBatch,
    float* __restrict__ C, int ldc, long cBatch,
    int M, int N, int K)
{
    A  += (long)blockIdx.z * aBatch;
    Bm += (long)blockIdx.z * bBatch;
    C  += (long)blockIdx.z * cBatch;

    __shared__ float As[BM][BK + 1];   // +1 pad vs store conflicts
    __shared__ float Bs[BK][BN];

    const int tid = threadIdx.x;
    const int tx = tid & 15;           // 0..15 -> N microtiles
    const int ty = tid >> 4;           // 0..15 -> M microtiles
    const int rowBase = blockIdx.y * BM;
    const int colBase = blockIdx.x * BN;

    float acc[8][8];
#pragma unroll
    for (int i = 0; i < 8; i++)
#pragma unroll
        for (int j = 0; j < 8; j++) acc[i][j] = 0.f;

    for (int k0 = 0; k0 < K; k0 += BK) {
        // A tile: 128 rows x 16 k. 16 consecutive threads read 16 consecutive k.
#pragma unroll
        for (int r = 0; r < 8; r++) {
            int idx = tid + r * 256;
            int arow = idx >> 4;
            int ak   = idx & 15;
            As[arow][ak] = A[(long)(rowBase + arow) * lda + k0 + ak];
        }
        // B tile: 16 k x 128 n, perfectly coalesced over n.
#pragma unroll
        for (int r = 0; r < 8; r++) {
            int idx = tid + r * 256;
            int bk = idx >> 7;
            int bn = idx & 127;
            Bs[bk][bn] = Bm[(long)(k0 + bk) * ldb + colBase + bn];
        }
        __syncthreads();

#pragma unroll
        for (int k = 0; k < BK; k++) {
            float a[8], b[8];
#pragma unroll
            for (int i = 0; i < 8; i++) a[i] = As[ty * 8 + i][k];
#pragma unroll
            for (int j = 0; j < 8; j++) b[j] = Bs[k][tx * 8 + j];
#pragma unroll
            for (int i = 0; i < 8; i++)
#pragma unroll
                for (int j = 0; j < 8; j++)
                    acc[i][j] = fmaf(a[i], b[j], acc[i][j]);
        }
        __syncthreads();
    }

#pragma unroll
    for (int i = 0; i < 8; i++)
#pragma unroll
        for (int j = 0; j < 8; j++)
            C[(long)(rowBase + ty * 8 + i) * ldc + colBase + tx * 8 + j] = acc[i][j];
}

// ---------------------------------------------------------------------------
// RMSNorm over 512 cols (q path). grid = B*QL rows, block = 256.
// ---------------------------------------------------------------------------
__global__ __launch_bounds__(256) void rmsnorm_q(
    float* __restrict__ x, const float* __restrict__ w)
{
    float* p = x + (long)blockIdx.x * QLR_;
    const int t = threadIdx.x;
    float v0 = p[t], v1 = p[t + 256];
    __shared__ float red[256];
    red[t] = v0 * v0 + v1 * v1;
    __syncthreads();
    for (int s = 128; s > 0; s >>= 1) {
        if (t < s) red[t] += red[t + s];
        __syncthreads();
    }
    float inv = rsqrtf(red[0] * (1.f / QLR_) + EPS_);
    p[t]       = v0 * inv * w[t];
    p[t + 256] = v1 * inv * w[t + 256];
}

// ---------------------------------------------------------------------------
// RMSNorm over LAT=256 per (row, group). grid = B*KL*G, block = 256.
// ---------------------------------------------------------------------------
__global__ __launch_bounds__(256) void rmsnorm_kv(
    float* __restrict__ x, const float* __restrict__ w)
{
    const int row = blockIdx.x >> 2;
    const int g   = blockIdx.x & 3;
    float* p = x + (long)row * (G_ * LAT_) + g * LAT_;
    const int t = threadIdx.x;
    float v = p[t];
    __shared__ float red[256];
    red[t] = v * v;
    __syncthreads();
    for (int s = 128; s > 0; s >>= 1) {
        if (t < s) red[t] += red[t + s];
        __syncthreads();
    }
    float inv = rsqrtf(red[0] * (1.f / LAT_) + EPS_);
    p[t] = v * inv * w[g * LAT_ + t];
}

// ---------------------------------------------------------------------------
// Flash attention, fp32, online softmax.
// grid: (QL/64, B*H). block: 256 threads (16x16).
// Q read from g_qfull (cols h*192+d), K/V strided from g_kv (h*256 + {d, 128+d}).
// ---------------------------------------------------------------------------
#define QT 64
#define KT 64
#define RSTR 129          // padded row stride for Q/K/V smem tiles
#define PSTR 65           // padded row stride for P tile
#define FLASH_SMEM ((3 * QT * RSTR + QT * PSTR) * 4)

__global__ __launch_bounds__(256) void flash_attn(
    const float* __restrict__ qfull,
    const float* __restrict__ kv,
    float* __restrict__ out)
{
    extern __shared__ float sm[];
    float* Qs = sm;                    // QT x RSTR
    float* Ks = Qs + QT * RSTR;        // KT x RSTR
    float* Vs = Ks + KT * RSTR;        // KT x RSTR
    float* Ps = Vs + KT * RSTR;        // QT x PSTR

    const int tid = threadIdx.x;
    const int tx = tid & 15;
    const int ty = tid >> 4;
    const int b = blockIdx.y >> 4;
    const int h = blockIdx.y & 15;
    const int q0 = blockIdx.x * QT;

    // Load Q tile [64 x 128]
    for (int i = tid; i < QT * HD_; i += 256) {
        int r = i >> 7, d = i & 127;
        Qs[r * RSTR + d] =
            qfull[(long)(b * QL_ + q0 + r) * (H_ * (HD_ + RD_)) + h * (HD_ + RD_) + d];
    }

    float acc[4][8];
#pragma unroll
    for (int i = 0; i < 4; i++)
#pragma unroll
        for (int j = 0; j < 8; j++) acc[i][j] = 0.f;
    float mrow[4], lrow[4];
#pragma unroll
    for (int i = 0; i < 4; i++) { mrow[i] = -1e30f; lrow[i] = 0.f; }

    const float scale = 0.08838834764831845f;   // 1/sqrt(128)

    for (int kt = 0; kt < KL_ / KT; kt++) {
        __syncthreads();   // protect Ks/Vs reuse (covers Q load on iter 0)
        for (int i = tid; i < KT * HD_; i += 256) {
            int c = i >> 7, d = i & 127;
            long base = (long)(b * KL_ + kt * KT + c) * (H_ * 2 * HD_) + h * (2 * HD_);
            Ks[c * RSTR + d] = kv[base + d];
            Vs[c * RSTR + d] = kv[base + HD_ + d];
        }
        __syncthreads();

        // S = Q K^T (4x4 per thread)
        float s[4][4];
#pragma unroll
        for (int i = 0; i < 4; i++)
#pragma unroll
            for (int j = 0; j < 4; j++) s[i][j] = 0.f;
        for (int d = 0; d < HD_; d++) {
            float qv[4], kk[4];
#pragma unroll
            for (int i = 0; i < 4; i++) qv[i] = Qs[(ty * 4 + i) * RSTR + d];
#pragma unroll
            for (int j = 0; j < 4; j++) kk[j] = Ks[(tx * 4 + j) * RSTR + d];
#pragma unroll
            for (int i = 0; i < 4; i++)
#pragma unroll
                for (int j = 0; j < 4; j++) s[i][j] = fmaf(qv[i], kk[j], s[i][j]);
        }

        // Online softmax update, per row (16 tx threads per row cooperate).
#pragma unroll
        for (int i = 0; i < 4; i++) {
            float mt = -1e30f;
#pragma unroll
            for (int j = 0; j < 4; j++) { s[i][j] *= scale; mt = fmaxf(mt, s[i][j]); }
            for (int off = 1; off < 16; off <<= 1)
                mt = fmaxf(mt, __shfl_xor_sync(0xffffffffu, mt, off));
            float mnew = fmaxf(mrow[i], mt);
            float corr = __expf(mrow[i] - mnew);
            mrow[i] = mnew;
            float ps = 0.f;
#pragma unroll
            for (int j = 0; j < 4; j++) {
                float p = __expf(s[i][j] - mnew);
                s[i][j] = p; ps += p;
            }
            for (int off = 1; off < 16; off <<= 1)
                ps += __shfl_xor_sync(0xffffffffu, ps, off);
            lrow[i] = lrow[i] * corr + ps;
#pragma unroll
            for (int j = 0; j < 8; j++) acc[i][j] *= corr;
#pragma unroll
            for (int j = 0; j < 4; j++)
                Ps[(ty * 4 + i) * PSTR + tx * 4 + j] = s[i][j];
        }
        __syncthreads();

        // O += P V  (each thread: rows ty*4.., dims tx*8..)
        for (int kc = 0; kc < KT; kc++) {
            float vv[8];
#pragma unroll
            for (int j = 0; j < 8; j++) vv[j] = Vs[kc * RSTR + tx * 8 + j];
#pragma unroll
            for (int i = 0; i < 4; i++) {
                float p = Ps[(ty * 4 + i) * PSTR + kc];
#pragma unroll
                for (int j = 0; j < 8; j++) acc[i][j] = fmaf(p, vv[j], acc[i][j]);
            }
        }
    }

    // Epilogue: normalize, write [B,QL,H*HD]
#pragma unroll
    for (int i = 0; i < 4; i++) {
        float inv = 1.f / lrow[i];
#pragma unroll
        for (int j = 0; j < 8; j++)
            out[(long)(b * QL_ + q0 + ty * 4 + i) * (H_ * HD_) + h * HD_ + tx * 8 + j]
                = acc[i][j] * inv;
    }
}

// ---------------------------------------------------------------------------
// Launch
// ---------------------------------------------------------------------------
extern "C" void kernel_launch(void* const* d_in, const int* in_sizes, int n_in,
                              void* d_out, int out_size)
{
    const float* x_q       = (const float*)d_in[0];
    const float* x_kv      = (const float*)d_in[1];
    const float* W_dQ      = (const float*)d_in[2];
    const float* q_norm_w  = (const float*)d_in[3];
    const float* W_uQ      = (const float*)d_in[4];
    const float* W_dKV     = (const float*)d_in[5];
    const float* kv_norm_w = (const float*)d_in[6];
    const float* W_ukv     = (const float*)d_in[7];
    const float* W_o       = (const float*)d_in[8];
    float* out = (float*)d_out;

    float *qlat, *qfull, *ckv, *kv, *attn;
    cudaGetSymbolAddress((void**)&qlat,  g_qlat);
    cudaGetSymbolAddress((void**)&qfull, g_qfull);
    cudaGetSymbolAddress((void**)&ckv,   g_ckv);
    cudaGetSymbolAddress((void**)&kv,    g_kv);
    cudaGetSymbolAddress((void**)&attn,  g_attn);

    const int M_q  = B_ * QL_;   // 2048
    const int M_kv = B_ * KL_;   // 8192

    // 1) q_lat = x_q @ W_dQ   [2048,2048]@[2048,512]
    gemm_f32<<<dim3(QLR_ / BN, M_q / BM, 1), 256>>>(
        x_q, HID_, 0, W_dQ, QLR_, 0, qlat, QLR_, 0, M_q, QLR_, HID_);

    // 2) rmsnorm(q_lat) in place
    rmsnorm_q<<<M_q, 256>>>(qlat, q_norm_w);

    // 3) q_full = q_lat @ W_uQ   [2048,512]@[512,3072]
    gemm_f32<<<dim3(3072 / BN, M_q / BM, 1), 256>>>(
        qlat, QLR_, 0, W_uQ, 3072, 0, qfull, 3072, 0, M_q, 3072, QLR_);

    // 4) ckv = (x_kv @ W_dKV)[:, :1024]   [8192,2048]@[2048,1088->1024]
    gemm_f32<<<dim3(1024 / BN, M_kv / BM, 1), 256>>>(
        x_kv, HID_, 0, W_dKV, 1088, 0, ckv, 1024, 0, M_kv, 1024, HID_);

    // 5) rmsnorm per (row, group) in place
    rmsnorm_kv<<<M_kv * G_, 256>>>(ckv, kv_norm_w);

    // 6) kv[:, g] = ckv[:, g] @ W_ukv[g]   batched over g (gridDim.z=4)
    gemm_f32<<<dim3(1024 / BN, M_kv / BM, G_), 256>>>(
        ckv, G_ * LAT_, LAT_,
        W_ukv, 1024, (long)LAT_ * 1024,
        kv, H_ * 2 * HD_, 1024,
        M_kv, 1024, LAT_);

    // 7) flash attention -> attn [2048, 2048]
    cudaFuncSetAttribute(flash_attn,
                         cudaFuncAttributeMaxDynamicSharedMemorySize, FLASH_SMEM);
    flash_attn<<<dim3(QL_ / QT, B_ * H_), 256, FLASH_SMEM>>>(qfull, kv, attn);

    // 8) out = attn @ W_o   [2048,2048]@[2048,2048]
    gemm_f32<<<dim3(HID_ / BN, M_q / BM, 1), 256>>>(
        attn, H_ * HD_, 0, W_o, HID_, 0, out, HID_, 0, M_q, HID_, H_ * HD_);
}